// round 14
// baseline (speedup 1.0000x reference)
#include <cuda_runtime.h>
#include <cuda_fp16.h>
#include <cooperative_groups.h>
#include <stdint.h>

namespace cg = cooperative_groups;

#define NN 150000
#define NE 2400000
#define NG 1024
#define F  32
#define GF (NG * F)
#define EPSV 1e-5f
#define PAD 64          // padded CSR bin width (P(deg>64) ~ 1e-19)

// ---------------- scratch (device globals; no runtime allocation) ----------
__device__ int   g_cursor[NN];
__device__ __align__(16) int g_csrc[NN * PAD];
__device__ __align__(16) float  g_dinv[NN];
__device__ float g_counts[NG];
__device__ __align__(16) float4 g_y4[NN];
__device__ __align__(16) __half g_hh[NN * F];
__device__ __align__(16) __half g_aggh[NN * F];
__device__ __align__(16) __half g_x1[NN * F];
__device__ __align__(16) __half g_x2[NN * F];
__device__ __align__(16) float  g_gsum[3][GF];
__device__ __align__(16) float  g_gsqs[3][GF];
__device__ __align__(16) float  g_pool[GF];

struct P {
    const float* x; const int* batch;
    const int* src; const int* dst;
    const float *W1, *b1, *g1w, *g1b, *g1m;
    const float *W2, *b2, *g2w, *g2b, *g2m;
    const float *W3, *b3, *g3w, *g3b, *g3m;
    const float *lw, *lb; float* out;
};

__device__ __forceinline__ void red4(float* p, float a, float b, float c, float d) {
    asm volatile("red.global.add.v4.f32 [%0], {%1,%2,%3,%4};"
                 :: "l"(p), "f"(a), "f"(b), "f"(c), "f"(d) : "memory");
}

__device__ __forceinline__ void addh8(float* acc, const __half* p) {
    uint4 u = *(const uint4*)p;
    float2 f0 = __half22float2(*(__half2*)&u.x);
    float2 f1 = __half22float2(*(__half2*)&u.y);
    float2 f2 = __half22float2(*(__half2*)&u.z);
    float2 f3 = __half22float2(*(__half2*)&u.w);
    acc[0] += f0.x; acc[1] += f0.y; acc[2] += f1.x; acc[3] += f1.y;
    acc[4] += f2.x; acc[5] += f2.y; acc[6] += f3.x; acc[7] += f3.y;
}

__device__ __forceinline__ void addquad8(float* acc, uint4 u0, uint4 u1,
                                         uint4 u2, uint4 u3) {
    __half2 a0 = __hadd2(*(__half2*)&u0.x, *(__half2*)&u1.x);
    __half2 a1 = __hadd2(*(__half2*)&u0.y, *(__half2*)&u1.y);
    __half2 a2 = __hadd2(*(__half2*)&u0.z, *(__half2*)&u1.z);
    __half2 a3 = __hadd2(*(__half2*)&u0.w, *(__half2*)&u1.w);
    __half2 b0 = __hadd2(*(__half2*)&u2.x, *(__half2*)&u3.x);
    __half2 b1 = __hadd2(*(__half2*)&u2.y, *(__half2*)&u3.y);
    __half2 b2 = __hadd2(*(__half2*)&u2.z, *(__half2*)&u3.z);
    __half2 b3 = __hadd2(*(__half2*)&u2.w, *(__half2*)&u3.w);
    a0 = __hadd2(a0, b0); a1 = __hadd2(a1, b1);
    a2 = __hadd2(a2, b2); a3 = __hadd2(a3, b3);
    float2 f0 = __half22float2(a0);
    float2 f1 = __half22float2(a1);
    float2 f2 = __half22float2(a2);
    float2 f3 = __half22float2(a3);
    acc[0] += f0.x; acc[1] += f0.y; acc[2] += f1.x; acc[3] += f1.y;
    acc[4] += f2.x; acc[5] += f2.y; acc[6] += f3.x; acc[7] += f3.y;
}

__device__ __forceinline__ float4 ldh4(const __half* p) {
    uint2 u = *(const uint2*)p;
    float2 f0 = __half22float2(*(__half2*)&u.x);
    float2 f1 = __half22float2(*(__half2*)&u.y);
    return make_float4(f0.x, f0.y, f1.x, f1.y);
}

__device__ __forceinline__ uint4 pack8(const float* v) {
    uint4 st;
    __half2 p0 = __floats2half2_rn(v[0], v[1]);
    __half2 p1 = __floats2half2_rn(v[2], v[3]);
    __half2 p2 = __floats2half2_rn(v[4], v[5]);
    __half2 p3 = __floats2half2_rn(v[6], v[7]);
    st.x = *(uint32_t*)&p0; st.y = *(uint32_t*)&p1;
    st.z = *(uint32_t*)&p2; st.w = *(uint32_t*)&p3;
    return st;
}

// ---- stats from per-thread v[8]/v2[8]; warp-aligned uni-graph fast path ----
__device__ __forceinline__ void stats_reduce(const int* __restrict__ batch,
                                             int t, int n, int c, int lane,
                                             float* v, float* v2,
                                             float* gsum, float* gsqs) {
    int nw0 = (t & ~31) >> 2;
    bool uni = (nw0 + 7 < NN) && (batch[nw0] == batch[nw0 + 7]);
    const unsigned FM = 0xffffffffu;
    if (uni) {
#pragma unroll
        for (int off = 4; off <= 16; off <<= 1) {
#pragma unroll
            for (int j = 0; j < 8; j++) {
                v[j]  += __shfl_xor_sync(FM, v[j],  off);
                v2[j] += __shfl_xor_sync(FM, v2[j], off);
            }
        }
        if (lane < 4) {
            int g = batch[nw0];
            red4(gsum + g * F + lane * 8,     v[0], v[1], v[2], v[3]);
            red4(gsum + g * F + lane * 8 + 4, v[4], v[5], v[6], v[7]);
            red4(gsqs + g * F + lane * 8,     v2[0], v2[1], v2[2], v2[3]);
            red4(gsqs + g * F + lane * 8 + 4, v2[4], v2[5], v2[6], v2[7]);
        }
    } else if (n < NN) {
        int g = batch[n];
        red4(gsum + g * F + c * 8,     v[0], v[1], v[2], v[3]);
        red4(gsum + g * F + c * 8 + 4, v[4], v[5], v[6], v[7]);
        red4(gsqs + g * F + c * 8,     v2[0], v2[1], v2[2], v2[3]);
        red4(gsqs + g * F + c * 8 + 4, v2[4], v2[5], v2[6], v2[7]);
    }
}

// ---- gather for layers 2/3 (fp16 rows) + fused stats -----------------------
__device__ void stage_gather(const int* __restrict__ batch,
                             const float* __restrict__ bL,
                             float* gsum, float* gsqs,
                             int tid, int T, int lane) {
    for (int t = tid; t < NN * 4; t += T) {
        int n = t >> 2;
        int c = t & 3;
        float acc[8] = {0,0,0,0,0,0,0,0};
        float v[8], v2[8];
        {
            float d = g_dinv[n];
            addh8(acc, g_hh + (size_t)n * F + c * 8);
            int base = n * PAD;
            int cnt = g_cursor[n] - base;
            const int* lp = g_csrc + base;
            int i = 0;
            for (; i + 7 < cnt; i += 8) {
                int4 s4 = *(const int4*)(lp + i);
                int4 s5 = *(const int4*)(lp + i + 4);
                uint4 u0 = *(const uint4*)(g_hh + (size_t)s4.x * F + c * 8);
                uint4 u1 = *(const uint4*)(g_hh + (size_t)s4.y * F + c * 8);
                uint4 u2 = *(const uint4*)(g_hh + (size_t)s4.z * F + c * 8);
                uint4 u3 = *(const uint4*)(g_hh + (size_t)s4.w * F + c * 8);
                uint4 u4 = *(const uint4*)(g_hh + (size_t)s5.x * F + c * 8);
                uint4 u5 = *(const uint4*)(g_hh + (size_t)s5.y * F + c * 8);
                uint4 u6 = *(const uint4*)(g_hh + (size_t)s5.z * F + c * 8);
                uint4 u7 = *(const uint4*)(g_hh + (size_t)s5.w * F + c * 8);
                addquad8(acc, u0, u1, u2, u3);
                addquad8(acc, u4, u5, u6, u7);
            }
            for (; i + 3 < cnt; i += 4) {
                int4 s4 = *(const int4*)(lp + i);
                uint4 u0 = *(const uint4*)(g_hh + (size_t)s4.x * F + c * 8);
                uint4 u1 = *(const uint4*)(g_hh + (size_t)s4.y * F + c * 8);
                uint4 u2 = *(const uint4*)(g_hh + (size_t)s4.z * F + c * 8);
                uint4 u3 = *(const uint4*)(g_hh + (size_t)s4.w * F + c * 8);
                addquad8(acc, u0, u1, u2, u3);
            }
            for (; i < cnt; i++)
                addh8(acc, g_hh + (size_t)lp[i] * F + c * 8);
            const float* bb = bL + c * 8;
#pragma unroll
            for (int j = 0; j < 8; j++) {
                v[j] = d * acc[j] + bb[j];
                v2[j] = v[j] * v[j];
            }
            *(uint4*)(g_aggh + (size_t)n * F + c * 8) = pack8(v);
        }
        stats_reduce(batch, t, n, c, lane, v, v2, gsum, gsqs);
    }
}

// ---- norm + next-layer lin; 8 nodes per warp --------------------------------
__device__ void stage_normlin(const int* __restrict__ batch,
                              const float* gsum, const float* gsqs,
                              const float* __restrict__ w,
                              const float* __restrict__ b,
                              const float* __restrict__ ms,
                              const __half* __restrict__ res,
                              const float* __restrict__ Wn,
                              __half* __restrict__ xout,
                              int warp_id, int TW, int lane) {
    float wreg[F];
#pragma unroll
    for (int k = 0; k < F; k++) wreg[k] = Wn[k * F + lane];
    float mw = ms[lane], ww = w[lane], bb = b[lane];
    for (int wi = warp_id; wi * 8 < NN; wi += TW) {
        int n0 = wi * 8;
#pragma unroll
        for (int it = 0; it < 8; it++) {
            int n = n0 + it;
            if (n >= NN) break;
            int g = batch[n];
            float inv = 1.f / g_counts[g];
            float xv = __half2float(g_aggh[(size_t)n * F + lane]);
            float s  = gsum[g * F + lane];
            float q  = gsqs[g * F + lane];
            float mean = s * inv;
            float ex2  = q * inv;
            float tv   = xv - mw * mean;
            float var  = ex2 - mw * (2.f - mw) * mean * mean;
            float o = ww * tv * rsqrtf(var + EPSV) + bb;
            if (res) o += __half2float(res[(size_t)n * F + lane]);
            o = fmaxf(o, 0.f);
            xout[(size_t)n * F + lane] = __float2half(o);
            float acc = 0.f;
#pragma unroll
            for (int k = 0; k < F; k++) {
                float ok = __shfl_sync(0xffffffffu, o, k);
                acc += ok * wreg[k];
            }
            g_hh[(size_t)n * F + lane] = __float2half(g_dinv[n] * acc);
        }
    }
}

// ---------------- the single cooperative kernel -------------------------------
__global__ void __launch_bounds__(256)
uber(P p) {
    cg::grid_group grid = cg::this_grid();
    const int tid = blockIdx.x * blockDim.x + threadIdx.x;
    const int T   = gridDim.x * blockDim.x;
    const int lane = threadIdx.x & 31;
    const int warp_id = tid >> 5;
    const int TW = T >> 5;

    __shared__ float sW[3 * F];
    __shared__ float sb[F];

    // stage 1: init cursors + zero stats/pool + counts
    for (int i = tid; i < NN; i += T) g_cursor[i] = i * PAD;
    for (int i = tid; i < GF; i += T) {
        g_pool[i] = 0.f;
#pragma unroll
        for (int l = 0; l < 3; l++) { g_gsum[l][i] = 0.f; g_gsqs[l][i] = 0.f; }
    }
    for (int i = tid; i < NG; i += T) {
        int lo = 0, hi = NN;
        while (lo < hi) { int m = (lo + hi) >> 1; if (p.batch[m] < i) lo = m + 1; else hi = m; }
        int lo2 = lo, hi2 = NN;
        while (lo2 < hi2) { int m = (lo2 + hi2) >> 1; if (p.batch[m] < i + 1) lo2 = m + 1; else hi2 = m; }
        g_counts[i] = (float)(lo2 - lo);
    }
    grid.sync();

    // stage 2: padded-CSR fill
    for (int t = tid; t < NE / 4; t += T) {
        int4 s = ((const int4*)p.src)[t];
        int4 d = ((const int4*)p.dst)[t];
        int p0 = atomicAdd(&g_cursor[d.x], 1);
        int p1 = atomicAdd(&g_cursor[d.y], 1);
        int p2 = atomicAdd(&g_cursor[d.z], 1);
        int p3 = atomicAdd(&g_cursor[d.w], 1);
        g_csrc[min(p0, d.x * PAD + PAD - 1)] = s.x;
        g_csrc[min(p1, d.y * PAD + PAD - 1)] = s.y;
        g_csrc[min(p2, d.z * PAD + PAD - 1)] = s.z;
        g_csrc[min(p3, d.w * PAD + PAD - 1)] = s.w;
    }
    grid.sync();

    // stage 3: dinv + y = dinv*x
    for (int n = tid; n < NN; n += T) {
        int deg = g_cursor[n] - n * PAD;
        float d = rsqrtf((float)deg + 1.f);
        g_dinv[n] = d;
        float x0 = p.x[n * 3 + 0], x1 = p.x[n * 3 + 1], x2 = p.x[n * 3 + 2];
        g_y4[n] = make_float4(d * x0, d * x1, d * x2, 0.f);
    }
    grid.sync();

    // stage 4: fused layer-1 gather + W1 transform -> aggh (fp16)
    for (int i = threadIdx.x; i < 3 * F; i += blockDim.x) sW[i] = p.W1[i];
    if (threadIdx.x < F) sb[threadIdx.x] = p.b1[threadIdx.x];
    __syncthreads();
    for (int n = tid; n < NN; n += T) {
        int base = n * PAD;
        int cnt = g_cursor[n] - base;
        const int* lp = g_csrc + base;
        float4 y = g_y4[n];
        float ax = y.x, ay = y.y, az = y.z;
        int i = 0;
        for (; i + 7 < cnt; i += 8) {
            int4 s0 = *(const int4*)(lp + i);
            int4 s1 = *(const int4*)(lp + i + 4);
            float4 a = g_y4[s0.x];
            float4 b = g_y4[s0.y];
            float4 c = g_y4[s0.z];
            float4 d = g_y4[s0.w];
            float4 e = g_y4[s1.x];
            float4 f = g_y4[s1.y];
            float4 g = g_y4[s1.z];
            float4 h = g_y4[s1.w];
            ax += ((a.x + b.x) + (c.x + d.x)) + ((e.x + f.x) + (g.x + h.x));
            ay += ((a.y + b.y) + (c.y + d.y)) + ((e.y + f.y) + (g.y + h.y));
            az += ((a.z + b.z) + (c.z + d.z)) + ((e.z + f.z) + (g.z + h.z));
        }
        for (; i + 3 < cnt; i += 4) {
            int4 s0 = *(const int4*)(lp + i);
            float4 a = g_y4[s0.x];
            float4 b = g_y4[s0.y];
            float4 c = g_y4[s0.z];
            float4 d = g_y4[s0.w];
            ax += (a.x + b.x) + (c.x + d.x);
            ay += (a.y + b.y) + (c.y + d.y);
            az += (a.z + b.z) + (c.z + d.z);
        }
        for (; i < cnt; i++) {
            float4 a = g_y4[lp[i]];
            ax += a.x; ay += a.y; az += a.z;
        }
        float d = g_dinv[n];
#pragma unroll
        for (int c = 0; c < 4; c++) {
            float v[8];
#pragma unroll
            for (int j = 0; j < 8; j++) {
                int col = c * 8 + j;
                v[j] = d * (ax * sW[col] + ay * sW[F + col] + az * sW[2 * F + col]) + sb[col];
            }
            *(uint4*)(g_aggh + (size_t)n * F + c * 8) = pack8(v);
        }
    }
    grid.sync();

    // stage 5: layer-1 stats from fp16 val
    for (int t = tid; t < NN * 4; t += T) {
        int n = t >> 2;
        int c = t & 3;
        float v[8], v2[8];
        float4 a = ldh4(g_aggh + (size_t)n * F + c * 8);
        float4 b = ldh4(g_aggh + (size_t)n * F + c * 8 + 4);
        v[0] = a.x; v[1] = a.y; v[2] = a.z; v[3] = a.w;
        v[4] = b.x; v[5] = b.y; v[6] = b.z; v[7] = b.w;
#pragma unroll
        for (int j = 0; j < 8; j++) v2[j] = v[j] * v[j];
        stats_reduce(p.batch, t, n, c, lane, v, v2, g_gsum[0], g_gsqs[0]);
    }
    grid.sync();

    // stage 6: norm1 + lin2
    stage_normlin(p.batch, g_gsum[0], g_gsqs[0], p.g1w, p.g1b, p.g1m,
                  nullptr, p.W2, g_x1, warp_id, TW, lane);
    grid.sync();

    // stage 7: gather layer 2 (+ stats)
    stage_gather(p.batch, p.b2, g_gsum[1], g_gsqs[1], tid, T, lane);
    grid.sync();

    // stage 8: norm2 + lin3
    stage_normlin(p.batch, g_gsum[1], g_gsqs[1], p.g2w, p.g2b, p.g2m,
                  g_x1, p.W3, g_x2, warp_id, TW, lane);
    grid.sync();

    // stage 9: gather layer 3 (+ stats)
    stage_gather(p.batch, p.b3, g_gsum[2], g_gsqs[2], tid, T, lane);
    grid.sync();

    // stage 10: norm3 + residual + relu + pool
    for (int t = tid; t < NN * 8; t += T) {
        int n = t >> 3;
        int c = t & 7;
        int g = p.batch[n];
        float inv = 1.f / g_counts[g];
        float4 x = ldh4(g_aggh + (size_t)n * F + c * 4);
        float4 s = *(const float4*)(g_gsum[2] + g * F + c * 4);
        float4 q = *(const float4*)(g_gsqs[2] + g * F + c * 4);
        float4 mw = *(const float4*)(p.g3m + c * 4);
        float4 ww = *(const float4*)(p.g3w + c * 4);
        float4 bb = *(const float4*)(p.g3b + c * 4);
        float4 r = ldh4(g_x2 + (size_t)n * F + c * 4);
        float4 o;
        float mean, ex2, tv, var;
        mean = s.x * inv; ex2 = q.x * inv; tv = x.x - mw.x * mean;
        var = ex2 - mw.x * (2.f - mw.x) * mean * mean;
        o.x = fmaxf(ww.x * tv * rsqrtf(var + EPSV) + bb.x + r.x, 0.f);
        mean = s.y * inv; ex2 = q.y * inv; tv = x.y - mw.y * mean;
        var = ex2 - mw.y * (2.f - mw.y) * mean * mean;
        o.y = fmaxf(ww.y * tv * rsqrtf(var + EPSV) + bb.y + r.y, 0.f);
        mean = s.z * inv; ex2 = q.z * inv; tv = x.z - mw.z * mean;
        var = ex2 - mw.z * (2.f - mw.z) * mean * mean;
        o.z = fmaxf(ww.z * tv * rsqrtf(var + EPSV) + bb.z + r.z, 0.f);
        mean = s.w * inv; ex2 = q.w * inv; tv = x.w - mw.w * mean;
        var = ex2 - mw.w * (2.f - mw.w) * mean * mean;
        o.w = fmaxf(ww.w * tv * rsqrtf(var + EPSV) + bb.w + r.w, 0.f);
        red4(g_pool + g * F + c * 4, o.x, o.y, o.z, o.w);
    }
    grid.sync();

    // stage 11: final linear head
    for (int g = tid; g < NG; g += T) {
        float inv = 1.f / g_counts[g];
        float o0 = p.lb[0], o1 = p.lb[1], o2 = p.lb[2];
#pragma unroll
        for (int k = 0; k < F; k++) {
            float pl = g_pool[g * F + k] * inv;
            o0 += pl * p.lw[k * 3 + 0];
            o1 += pl * p.lw[k * 3 + 1];
            o2 += pl * p.lw[k * 3 + 2];
        }
        p.out[g * 3 + 0] = o0;
        p.out[g * 3 + 1] = o1;
        p.out[g * 3 + 2] = o2;
    }
}

// ---------------- host orchestration ------------------------------------------
extern "C" void kernel_launch(void* const* d_in, const int* in_sizes, int n_in,
                              void* d_out, int out_size) {
    P p;
    p.x     = (const float*)d_in[0];
    const int* eidx = (const int*)d_in[1];
    p.batch = (const int*)d_in[2];
    p.W1 = (const float*)d_in[3];  p.b1 = (const float*)d_in[4];
    p.g1w = (const float*)d_in[5]; p.g1b = (const float*)d_in[6]; p.g1m = (const float*)d_in[7];
    p.W2 = (const float*)d_in[8];  p.b2 = (const float*)d_in[9];
    p.g2w = (const float*)d_in[10]; p.g2b = (const float*)d_in[11]; p.g2m = (const float*)d_in[12];
    p.W3 = (const float*)d_in[13]; p.b3 = (const float*)d_in[14];
    p.g3w = (const float*)d_in[15]; p.g3b = (const float*)d_in[16]; p.g3m = (const float*)d_in[17];
    p.lw = (const float*)d_in[18]; p.lb = (const float*)d_in[19];
    p.out = (float*)d_out;
    p.src = eidx;
    p.dst = eidx + NE;

    int dev = 0;
    cudaGetDevice(&dev);
    int sms = 0;
    cudaDeviceGetAttribute(&sms, cudaDevAttrMultiProcessorCount, dev);
    int maxb = 0;
    cudaOccupancyMaxActiveBlocksPerMultiprocessor(&maxb, (const void*)uber, 256, 0);
    if (maxb < 1) maxb = 1;
    int grid = sms * maxb;
    if (grid < 1) grid = 148;

    void* args[] = { &p };
    cudaLaunchCooperativeKernel((const void*)uber, dim3(grid), dim3(256),
                                args, 0, (cudaStream_t)0);
}

// round 15
// speedup vs baseline: 8.4650x; 8.4650x over previous
#include <cuda_runtime.h>
#include <cuda_fp16.h>
#include <stdint.h>

#define NN 150000
#define NE 2400000
#define NG 1024
#define F  32
#define GF (NG * F)
#define EPSV 1e-5f
#define PAD 64          // padded CSR bin width (P(deg>64) ~ 1e-19)

#define GDC_WAIT()   asm volatile("griddepcontrol.wait;" ::: "memory")
#define GDC_LAUNCH() asm volatile("griddepcontrol.launch_dependents;" ::: "memory")

// ---------------- scratch (device globals; no runtime allocation) ----------
__device__ int   g_cursor[NN];                  // starts at n*PAD; final = n*PAD+deg
__device__ __align__(16) int g_csrc[NN * PAD];  // padded neighbor lists
__device__ __align__(16) float  g_dinv[NN];
__device__ float g_counts[NG];
__device__ __align__(16) float4 g_y4[NN];       // layer-1: dinv*x padded to float4
__device__ __align__(16) __half g_hh[NN * F];   // hs = dinv*h, fp16 (layers 2,3)
__device__ __align__(16) __half g_aggh[NN * F]; // val, fp16
__device__ __align__(16) __half g_x1[NN * F];   // residuals, fp16
__device__ __align__(16) __half g_x2[NN * F];
__device__ __align__(16) float  g_gsum[3][GF];
__device__ __align__(16) float  g_gsqs[3][GF];
__device__ __align__(16) float  g_pool[GF];

__device__ __forceinline__ void red4(float* p, float a, float b, float c, float d) {
    asm volatile("red.global.add.v4.f32 [%0], {%1,%2,%3,%4};"
                 :: "l"(p), "f"(a), "f"(b), "f"(c), "f"(d) : "memory");
}

__device__ __forceinline__ void addh8(float* acc, const __half* p) {
    uint4 u = *(const uint4*)p;
    float2 f0 = __half22float2(*(__half2*)&u.x);
    float2 f1 = __half22float2(*(__half2*)&u.y);
    float2 f2 = __half22float2(*(__half2*)&u.z);
    float2 f3 = __half22float2(*(__half2*)&u.w);
    acc[0] += f0.x; acc[1] += f0.y; acc[2] += f1.x; acc[3] += f1.y;
    acc[4] += f2.x; acc[5] += f2.y; acc[6] += f3.x; acc[7] += f3.y;
}

__device__ __forceinline__ void addquad8(float* acc, uint4 u0, uint4 u1,
                                         uint4 u2, uint4 u3) {
    __half2 a0 = __hadd2(*(__half2*)&u0.x, *(__half2*)&u1.x);
    __half2 a1 = __hadd2(*(__half2*)&u0.y, *(__half2*)&u1.y);
    __half2 a2 = __hadd2(*(__half2*)&u0.z, *(__half2*)&u1.z);
    __half2 a3 = __hadd2(*(__half2*)&u0.w, *(__half2*)&u1.w);
    __half2 b0 = __hadd2(*(__half2*)&u2.x, *(__half2*)&u3.x);
    __half2 b1 = __hadd2(*(__half2*)&u2.y, *(__half2*)&u3.y);
    __half2 b2 = __hadd2(*(__half2*)&u2.z, *(__half2*)&u3.z);
    __half2 b3 = __hadd2(*(__half2*)&u2.w, *(__half2*)&u3.w);
    a0 = __hadd2(a0, b0); a1 = __hadd2(a1, b1);
    a2 = __hadd2(a2, b2); a3 = __hadd2(a3, b3);
    float2 f0 = __half22float2(a0);
    float2 f1 = __half22float2(a1);
    float2 f2 = __half22float2(a2);
    float2 f3 = __half22float2(a3);
    acc[0] += f0.x; acc[1] += f0.y; acc[2] += f1.x; acc[3] += f1.y;
    acc[4] += f2.x; acc[5] += f2.y; acc[6] += f3.x; acc[7] += f3.y;
}

__device__ __forceinline__ float4 ldh4(const __half* p) {
    uint2 u = *(const uint2*)p;
    float2 f0 = __half22float2(*(__half2*)&u.x);
    float2 f1 = __half22float2(*(__half2*)&u.y);
    return make_float4(f0.x, f0.y, f1.x, f1.y);
}

__device__ __forceinline__ uint4 pack8(const float* v) {
    uint4 st;
    __half2 p0 = __floats2half2_rn(v[0], v[1]);
    __half2 p1 = __floats2half2_rn(v[2], v[3]);
    __half2 p2 = __floats2half2_rn(v[4], v[5]);
    __half2 p3 = __floats2half2_rn(v[6], v[7]);
    st.x = *(uint32_t*)&p0; st.y = *(uint32_t*)&p1;
    st.z = *(uint32_t*)&p2; st.w = *(uint32_t*)&p3;
    return st;
}

// ---------------- launch 1: init cursors + zero stats + counts ----------------
__global__ void k_pre(const int* __restrict__ batch) {
    int i = blockIdx.x * blockDim.x + threadIdx.x;
    if (i < NN) g_cursor[i] = i * PAD;
    if (i < GF) {
        g_pool[i] = 0.f;
#pragma unroll
        for (int l = 0; l < 3; l++) { g_gsum[l][i] = 0.f; g_gsqs[l][i] = 0.f; }
    }
    if (i < NG) {
        int lo = 0, hi = NN;
        while (lo < hi) { int m = (lo + hi) >> 1; if (batch[m] < i) lo = m + 1; else hi = m; }
        int lo2 = lo, hi2 = NN;
        while (lo2 < hi2) { int m = (lo2 + hi2) >> 1; if (batch[m] < i + 1) lo2 = m + 1; else hi2 = m; }
        g_counts[i] = (float)(lo2 - lo);
    }
    GDC_LAUNCH();
}

// ---------------- launch 2: padded-CSR fill ------------------------------------
__global__ void k_fill(const int* __restrict__ src, const int* __restrict__ dst) {
    GDC_WAIT();
    int t = blockIdx.x * blockDim.x + threadIdx.x;
    if (t < NE / 4) {
        int4 s = ((const int4*)src)[t];
        int4 d = ((const int4*)dst)[t];
        int p0 = atomicAdd(&g_cursor[d.x], 1);
        int p1 = atomicAdd(&g_cursor[d.y], 1);
        int p2 = atomicAdd(&g_cursor[d.z], 1);
        int p3 = atomicAdd(&g_cursor[d.w], 1);
        g_csrc[min(p0, d.x * PAD + PAD - 1)] = s.x;
        g_csrc[min(p1, d.y * PAD + PAD - 1)] = s.y;
        g_csrc[min(p2, d.z * PAD + PAD - 1)] = s.z;
        g_csrc[min(p3, d.w * PAD + PAD - 1)] = s.w;
    }
    GDC_LAUNCH();
}

// ---------------- launch 3: dinv + y = dinv*x -----------------------------------
__global__ void k_prep1(const float* __restrict__ x) {
    GDC_WAIT();
    int n = blockIdx.x * blockDim.x + threadIdx.x;
    if (n < NN) {
        int deg = g_cursor[n] - n * PAD;
        float d = rsqrtf((float)deg + 1.f);
        g_dinv[n] = d;
        float x0 = x[n * 3 + 0], x1 = x[n * 3 + 1], x2 = x[n * 3 + 2];
        g_y4[n] = make_float4(d * x0, d * x1, d * x2, 0.f);
    }
    GDC_LAUNCH();
}

// ---------------- launch 4: fused layer-1 gather + W1 transform -----------------
__global__ void k_g1lin(const float* __restrict__ W,    // [3,32]
                        const float* __restrict__ bL) { // [32]
    __shared__ float sW[3 * F];
    __shared__ float sb[F];
    GDC_WAIT();
    for (int i = threadIdx.x; i < 3 * F; i += blockDim.x) sW[i] = W[i];
    if (threadIdx.x < F) sb[threadIdx.x] = bL[threadIdx.x];
    __syncthreads();
    int n = blockIdx.x * blockDim.x + threadIdx.x;
    if (n < NN) {
        int base = n * PAD;
        int cnt = g_cursor[n] - base;
        const int* lp = g_csrc + base;
        float4 y = g_y4[n];
        float ax = y.x, ay = y.y, az = y.z;
        int i = 0;
        for (; i + 7 < cnt; i += 8) {
            int4 s0 = *(const int4*)(lp + i);
            int4 s1 = *(const int4*)(lp + i + 4);
            float4 a = g_y4[s0.x];
            float4 b = g_y4[s0.y];
            float4 c = g_y4[s0.z];
            float4 d = g_y4[s0.w];
            float4 e = g_y4[s1.x];
            float4 f = g_y4[s1.y];
            float4 g = g_y4[s1.z];
            float4 h = g_y4[s1.w];
            ax += ((a.x + b.x) + (c.x + d.x)) + ((e.x + f.x) + (g.x + h.x));
            ay += ((a.y + b.y) + (c.y + d.y)) + ((e.y + f.y) + (g.y + h.y));
            az += ((a.z + b.z) + (c.z + d.z)) + ((e.z + f.z) + (g.z + h.z));
        }
        for (; i + 3 < cnt; i += 4) {
            int4 s0 = *(const int4*)(lp + i);
            float4 a = g_y4[s0.x];
            float4 b = g_y4[s0.y];
            float4 c = g_y4[s0.z];
            float4 d = g_y4[s0.w];
            ax += (a.x + b.x) + (c.x + d.x);
            ay += (a.y + b.y) + (c.y + d.y);
            az += (a.z + b.z) + (c.z + d.z);
        }
        for (; i < cnt; i++) {
            float4 a = g_y4[lp[i]];
            ax += a.x; ay += a.y; az += a.z;
        }
        float d = g_dinv[n];
#pragma unroll
        for (int c = 0; c < 4; c++) {
            float v[8];
#pragma unroll
            for (int j = 0; j < 8; j++) {
                int col = c * 8 + j;
                v[j] = d * (ax * sW[col] + ay * sW[F + col] + az * sW[2 * F + col]) + sb[col];
            }
            *(uint4*)(g_aggh + (size_t)n * F + c * 8) = pack8(v);
        }
    }
    GDC_LAUNCH();
}

// ---------------- launch 5: layer-1 stats from fp16 val -------------------------
__global__ void k_stats1(const int* __restrict__ batch,
                         float* __restrict__ gsum,
                         float* __restrict__ gsqs) {
    GDC_WAIT();
    int tid = threadIdx.x;
    int t = blockIdx.x * blockDim.x + tid;
    int n = t >> 2;
    int c = t & 3;
    int lane = tid & 31;
    float v[8], v2[8];
    if (n < NN) {
        float4 a = ldh4(g_aggh + (size_t)n * F + c * 8);
        float4 b = ldh4(g_aggh + (size_t)n * F + c * 8 + 4);
        v[0] = a.x; v[1] = a.y; v[2] = a.z; v[3] = a.w;
        v[4] = b.x; v[5] = b.y; v[6] = b.z; v[7] = b.w;
#pragma unroll
        for (int j = 0; j < 8; j++) v2[j] = v[j] * v[j];
    } else {
#pragma unroll
        for (int j = 0; j < 8; j++) { v[j] = 0.f; v2[j] = 0.f; }
    }
    int nw0 = (blockIdx.x * blockDim.x + (tid & ~31)) >> 2;
    bool uni = (nw0 + 7 < NN) && (batch[nw0] == batch[nw0 + 7]);
    const unsigned FM = 0xffffffffu;
    if (uni) {
#pragma unroll
        for (int off = 4; off <= 16; off <<= 1) {
#pragma unroll
            for (int j = 0; j < 8; j++) {
                v[j]  += __shfl_xor_sync(FM, v[j],  off);
                v2[j] += __shfl_xor_sync(FM, v2[j], off);
            }
        }
        if (lane < 4) {
            int g = batch[nw0];
            red4(gsum + g * F + lane * 8,     v[0], v[1], v[2], v[3]);
            red4(gsum + g * F + lane * 8 + 4, v[4], v[5], v[6], v[7]);
            red4(gsqs + g * F + lane * 8,     v2[0], v2[1], v2[2], v2[3]);
            red4(gsqs + g * F + lane * 8 + 4, v2[4], v2[5], v2[6], v2[7]);
        }
    } else if (n < NN) {
        int g = batch[n];
        red4(gsum + g * F + c * 8,     v[0], v[1], v[2], v[3]);
        red4(gsum + g * F + c * 8 + 4, v[4], v[5], v[6], v[7]);
        red4(gsqs + g * F + c * 8,     v2[0], v2[1], v2[2], v2[3]);
        red4(gsqs + g * F + c * 8 + 4, v2[4], v2[5], v2[6], v2[7]);
    }
    GDC_LAUNCH();
}

// ---------------- gather layers 2/3: fp16 rows, 8-row MLP, fused stats ----------
__global__ void k_gather(const int* __restrict__ batch,
                         const float* __restrict__ bL,
                         float* __restrict__ gsum,
                         float* __restrict__ gsqs) {
    GDC_WAIT();
    int tid = threadIdx.x;
    int t = blockIdx.x * blockDim.x + tid;
    int n = t >> 2;
    int c = t & 3;
    int lane = tid & 31;
    float acc[8] = {0,0,0,0,0,0,0,0};
    float v[8], v2[8];
    if (n < NN) {
        float d = g_dinv[n];
        addh8(acc, g_hh + (size_t)n * F + c * 8);
        int base = n * PAD;
        int cnt = g_cursor[n] - base;
        const int* lp = g_csrc + base;
        int i = 0;
        for (; i + 7 < cnt; i += 8) {
            int4 s4 = *(const int4*)(lp + i);
            int4 s5 = *(const int4*)(lp + i + 4);
            uint4 u0 = *(const uint4*)(g_hh + (size_t)s4.x * F + c * 8);
            uint4 u1 = *(const uint4*)(g_hh + (size_t)s4.y * F + c * 8);
            uint4 u2 = *(const uint4*)(g_hh + (size_t)s4.z * F + c * 8);
            uint4 u3 = *(const uint4*)(g_hh + (size_t)s4.w * F + c * 8);
            uint4 u4 = *(const uint4*)(g_hh + (size_t)s5.x * F + c * 8);
            uint4 u5 = *(const uint4*)(g_hh + (size_t)s5.y * F + c * 8);
            uint4 u6 = *(const uint4*)(g_hh + (size_t)s5.z * F + c * 8);
            uint4 u7 = *(const uint4*)(g_hh + (size_t)s5.w * F + c * 8);
            addquad8(acc, u0, u1, u2, u3);
            addquad8(acc, u4, u5, u6, u7);
        }
        for (; i + 3 < cnt; i += 4) {
            int4 s4 = *(const int4*)(lp + i);
            uint4 u0 = *(const uint4*)(g_hh + (size_t)s4.x * F + c * 8);
            uint4 u1 = *(const uint4*)(g_hh + (size_t)s4.y * F + c * 8);
            uint4 u2 = *(const uint4*)(g_hh + (size_t)s4.z * F + c * 8);
            uint4 u3 = *(const uint4*)(g_hh + (size_t)s4.w * F + c * 8);
            addquad8(acc, u0, u1, u2, u3);
        }
        for (; i < cnt; i++)
            addh8(acc, g_hh + (size_t)lp[i] * F + c * 8);
        const float* bb = bL + c * 8;
#pragma unroll
        for (int j = 0; j < 8; j++) {
            v[j] = d * acc[j] + bb[j];
            v2[j] = v[j] * v[j];
        }
        *(uint4*)(g_aggh + (size_t)n * F + c * 8) = pack8(v);
    } else {
#pragma unroll
        for (int j = 0; j < 8; j++) { v[j] = 0.f; v2[j] = 0.f; }
    }
    int nw0 = (blockIdx.x * blockDim.x + (tid & ~31)) >> 2;
    bool uni = (nw0 + 7 < NN) && (batch[nw0] == batch[nw0 + 7]);
    const unsigned FM = 0xffffffffu;
    if (uni) {
#pragma unroll
        for (int off = 4; off <= 16; off <<= 1) {
#pragma unroll
            for (int j = 0; j < 8; j++) {
                v[j]  += __shfl_xor_sync(FM, v[j],  off);
                v2[j] += __shfl_xor_sync(FM, v2[j], off);
            }
        }
        if (lane < 4) {
            int g = batch[nw0];
            red4(gsum + g * F + lane * 8,     v[0], v[1], v[2], v[3]);
            red4(gsum + g * F + lane * 8 + 4, v[4], v[5], v[6], v[7]);
            red4(gsqs + g * F + lane * 8,     v2[0], v2[1], v2[2], v2[3]);
            red4(gsqs + g * F + lane * 8 + 4, v2[4], v2[5], v2[6], v2[7]);
        }
    } else if (n < NN) {
        int g = batch[n];
        red4(gsum + g * F + c * 8,     v[0], v[1], v[2], v[3]);
        red4(gsum + g * F + c * 8 + 4, v[4], v[5], v[6], v[7]);
        red4(gsqs + g * F + c * 8,     v2[0], v2[1], v2[2], v2[3]);
        red4(gsqs + g * F + c * 8 + 4, v2[4], v2[5], v2[6], v2[7]);
    }
    GDC_LAUNCH();
}

// ---------------- fused norm + next-layer lin; 8 nodes per warp -----------------
__global__ void k_normlin(const int* __restrict__ batch,
                          const float* __restrict__ gsum,
                          const float* __restrict__ gsqs,
                          const float* __restrict__ w,
                          const float* __restrict__ b,
                          const float* __restrict__ ms,
                          const __half* __restrict__ res,  // may be null
                          const float* __restrict__ Wn,    // [32,32]
                          __half* __restrict__ xout) {
    GDC_WAIT();
    int wid = threadIdx.x >> 5;
    int lane = threadIdx.x & 31;
    float wreg[F];
#pragma unroll
    for (int k = 0; k < F; k++) wreg[k] = Wn[k * F + lane];
    float mw = ms[lane], ww = w[lane], bb = b[lane];
    int n0 = (blockIdx.x * 8 + wid) * 8;
#pragma unroll
    for (int it = 0; it < 8; it++) {
        int n = n0 + it;
        if (n >= NN) break;
        int g = batch[n];
        float inv = 1.f / g_counts[g];
        float xv = __half2float(g_aggh[(size_t)n * F + lane]);
        float s  = gsum[g * F + lane];
        float q  = gsqs[g * F + lane];
        float mean = s * inv;
        float ex2  = q * inv;
        float tv   = xv - mw * mean;
        float var  = ex2 - mw * (2.f - mw) * mean * mean;
        float o = ww * tv * rsqrtf(var + EPSV) + bb;
        if (res) o += __half2float(res[(size_t)n * F + lane]);
        o = fmaxf(o, 0.f);
        xout[(size_t)n * F + lane] = __float2half(o);
        float acc = 0.f;
#pragma unroll
        for (int k = 0; k < F; k++) {
            float ok = __shfl_sync(0xffffffffu, o, k);
            acc += ok * wreg[k];
        }
        g_hh[(size_t)n * F + lane] = __float2half(g_dinv[n] * acc);
    }
    GDC_LAUNCH();
}

// ---------------- layer-3 norm + residual + relu + pool red ---------------------
__global__ void k_normpool(const int* __restrict__ batch,
                           const float* __restrict__ gsum,
                           const float* __restrict__ gsqs,
                           const float* __restrict__ w,
                           const float* __restrict__ b,
                           const float* __restrict__ ms,
                           const __half* __restrict__ res) {
    GDC_WAIT();
    int t = blockIdx.x * blockDim.x + threadIdx.x;
    int n = t >> 3;
    int c = t & 7;
    if (n < NN) {
        int g = batch[n];
        float inv = 1.f / g_counts[g];
        float4 x = ldh4(g_aggh + (size_t)n * F + c * 4);
        float4 s = *(const float4*)(gsum + g * F + c * 4);
        float4 q = *(const float4*)(gsqs + g * F + c * 4);
        float4 mw = *(const float4*)(ms + c * 4);
        float4 ww = *(const float4*)(w + c * 4);
        float4 bb = *(const float4*)(b + c * 4);
        float4 r = ldh4(res + (size_t)n * F + c * 4);
        float4 o;
        float mean, ex2, tv, var;
        mean = s.x * inv; ex2 = q.x * inv; tv = x.x - mw.x * mean;
        var = ex2 - mw.x * (2.f - mw.x) * mean * mean;
        o.x = fmaxf(ww.x * tv * rsqrtf(var + EPSV) + bb.x + r.x, 0.f);
        mean = s.y * inv; ex2 = q.y * inv; tv = x.y - mw.y * mean;
        var = ex2 - mw.y * (2.f - mw.y) * mean * mean;
        o.y = fmaxf(ww.y * tv * rsqrtf(var + EPSV) + bb.y + r.y, 0.f);
        mean = s.z * inv; ex2 = q.z * inv; tv = x.z - mw.z * mean;
        var = ex2 - mw.z * (2.f - mw.z) * mean * mean;
        o.z = fmaxf(ww.z * tv * rsqrtf(var + EPSV) + bb.z + r.z, 0.f);
        mean = s.w * inv; ex2 = q.w * inv; tv = x.w - mw.w * mean;
        var = ex2 - mw.w * (2.f - mw.w) * mean * mean;
        o.w = fmaxf(ww.w * tv * rsqrtf(var + EPSV) + bb.w + r.w, 0.f);
        red4(g_pool + g * F + c * 4, o.x, o.y, o.z, o.w);
    }
    GDC_LAUNCH();
}

// ---------------- final linear head ----------------------------------------------
__global__ void k_final(const float* __restrict__ lw,
                        const float* __restrict__ lb,
                        float* __restrict__ out) {
    __shared__ float sw[F * 3];
    GDC_WAIT();
    for (int i = threadIdx.x; i < F * 3; i += blockDim.x) sw[i] = lw[i];
    __syncthreads();
    int g = blockIdx.x * blockDim.x + threadIdx.x;
    if (g >= NG) return;
    float inv = 1.f / g_counts[g];
    float o0 = lb[0], o1 = lb[1], o2 = lb[2];
#pragma unroll
    for (int k = 0; k < F; k++) {
        float p = g_pool[g * F + k] * inv;
        o0 += p * sw[k * 3 + 0];
        o1 += p * sw[k * 3 + 1];
        o2 += p * sw[k * 3 + 2];
    }
    out[g * 3 + 0] = o0;
    out[g * 3 + 1] = o1;
    out[g * 3 + 2] = o2;
}

// ---------------- PDL launch helper ------------------------------------------------
template <typename K, typename... Args>
static void launch_pdl(K k, int grid, int block, Args... args) {
    cudaLaunchConfig_t cfg = {};
    cfg.gridDim = dim3(grid);
    cfg.blockDim = dim3(block);
    cfg.dynamicSmemBytes = 0;
    cfg.stream = (cudaStream_t)0;
    cudaLaunchAttribute attr[1];
    attr[0].id = cudaLaunchAttributeProgrammaticStreamSerialization;
    attr[0].val.programmaticStreamSerializationAllowed = 1;
    cfg.attrs = attr;
    cfg.numAttrs = 1;
    cudaLaunchKernelEx(&cfg, k, args...);
}

// ---------------- host orchestration ------------------------------------------------
extern "C" void kernel_launch(void* const* d_in, const int* in_sizes, int n_in,
                              void* d_out, int out_size) {
    const float* x     = (const float*)d_in[0];
    const int*   eidx  = (const int*)d_in[1];
    const int*   batch = (const int*)d_in[2];
    const float* W1  = (const float*)d_in[3];
    const float* b1  = (const float*)d_in[4];
    const float* g1w = (const float*)d_in[5];
    const float* g1b = (const float*)d_in[6];
    const float* g1m = (const float*)d_in[7];
    const float* W2  = (const float*)d_in[8];
    const float* b2  = (const float*)d_in[9];
    const float* g2w = (const float*)d_in[10];
    const float* g2b = (const float*)d_in[11];
    const float* g2m = (const float*)d_in[12];
    const float* W3  = (const float*)d_in[13];
    const float* b3  = (const float*)d_in[14];
    const float* g3w = (const float*)d_in[15];
    const float* g3b = (const float*)d_in[16];
    const float* g3m = (const float*)d_in[17];
    const float* lw  = (const float*)d_in[18];
    const float* lb  = (const float*)d_in[19];
    float* out = (float*)d_out;

    const int* src = eidx;
    const int* dst = eidx + NE;

    __half *px1, *px2;
    float *psum, *psqs;
    cudaGetSymbolAddress((void**)&px1, g_x1);
    cudaGetSymbolAddress((void**)&px2, g_x2);
    cudaGetSymbolAddress((void**)&psum, g_gsum);
    cudaGetSymbolAddress((void**)&psqs, g_gsqs);

    const int NB_NODE  = (NN + 255) / 256;
    const int NB_E4    = (NE / 4 + 255) / 256;
    const int NB_NODE4 = (NN * 4 + 255) / 256;
    const int NB_NODE8 = (NN * 8 + 255) / 256;
    const int NB_NL    = (NN + 63) / 64;

    launch_pdl(k_pre,   NB_NODE, 256, batch);
    launch_pdl(k_fill,  NB_E4,   256, src, dst);
    launch_pdl(k_prep1, NB_NODE, 256, x);
    launch_pdl(k_g1lin, NB_NODE, 256, W1, b1);
    launch_pdl(k_stats1, NB_NODE4, 256, batch,
               (float*)(psum + 0 * GF), (float*)(psqs + 0 * GF));
    launch_pdl(k_normlin, NB_NL, 256, batch,
               (const float*)(psum + 0 * GF), (const float*)(psqs + 0 * GF),
               g1w, g1b, g1m, (const __half*)nullptr, W2, px1);
    launch_pdl(k_gather, NB_NODE4, 256, batch, b2,
               (float*)(psum + 1 * GF), (float*)(psqs + 1 * GF));
    launch_pdl(k_normlin, NB_NL, 256, batch,
               (const float*)(psum + 1 * GF), (const float*)(psqs + 1 * GF),
               g2w, g2b, g2m, (const __half*)px1, W3, px2);
    launch_pdl(k_gather, NB_NODE4, 256, batch, b3,
               (float*)(psum + 2 * GF), (float*)(psqs + 2 * GF));
    launch_pdl(k_normpool, NB_NODE8, 256, batch,
               (const float*)(psum + 2 * GF), (const float*)(psqs + 2 * GF),
               g3w, g3b, g3m, (const __half*)px2);
    launch_pdl(k_final, (NG + 255) / 256, 256, lw, lb, out);
}